// round 8
// baseline (speedup 1.0000x reference)
#include <cuda_runtime.h>
#include <cstdint>

#define B_ 32
#define L_ 2048
#define S_ 8
#define HALO 8
#define OUT_ROWS ((L_ - 1) * (S_ + 1) + 1)   // 18424
#define TILE_L 64
#define ROWS_T (TILE_L + HALO)               // 72

// region A (phase 1): WBs[64][32][4] = 8192 floats, Fs[72*64] = 4608 floats
// region B (phase 2): Ps[72*64] + Qs[72*64] = 9216 floats, ALIASED over region A
#define SMEM_FLOATS (8192 + ROWS_T * 64)
#define FUSED_SMEM (SMEM_FLOATS * sizeof(float))   // 51200 B -> 4 blocks/SM

typedef unsigned long long u64;

__device__ __forceinline__ void fma2(u64& d, u64 a, u64 b) {
    asm("fma.rn.f32x2 %0, %1, %2, %0;" : "+l"(d) : "l"(a), "l"(b));
}
__device__ __forceinline__ u64 mul2(u64 a, u64 b) {
    u64 r;
    asm("mul.rn.f32x2 %0, %1, %2;" : "=l"(r) : "l"(a), "l"(b));
    return r;
}
__device__ __forceinline__ u64 splat2(float f) {
    u64 r;
    asm("mov.b64 %0, {%1, %1};" : "=l"(r) : "f"(f));
    return r;
}

// non_pad_mask dtype probe. lengths >= L/2 so mask[0,0], mask[0,1] are true.
// u8: [1,1,..] | i32: [1,0,0,0,..] | f32: [0,0,0x80,0x3f]
__device__ __forceinline__ int mask_kind(const unsigned char* m) {
    unsigned char b0 = m[0], b1 = m[1];
    if (b0 == 1 && b1 != 0) return 0;
    if (b0 == 1) return 1;
    return 2;
}

__global__ __launch_bounds__(256, 4) void fused_kernel(const float* __restrict__ times,
                                                       const float* __restrict__ F,
                                                       const void* __restrict__ maskp,
                                                       const float* __restrict__ usample,
                                                       const float* __restrict__ W,
                                                       const float* __restrict__ bias,
                                                       float* __restrict__ out) {
    extern __shared__ __align__(16) float smem[];
    float* WBs = smem;                         // [c][o2][4]: {W[2o2][c],W[2o2+1][c],B[c][2o2],B[c][2o2+1]}
    float* Fs  = smem + 8192;                  // 72 x 64
    // phase-2 aliases (valid only after the post-GEMM sync). Hold MASKED m_j*P, m_j*Q.
    float* Ps = smem;                          // 72 x 64
    float* Qs = smem + ROWS_T * 64;            // 72 x 64
    __shared__ float ts[ROWS_T + 1];
    __shared__ float vsf[ROWS_T + 1];          // mask as float 0/1
    __shared__ float us[S_];

    int tid = threadIdx.x;
    int b = blockIdx.y;
    int tileStart = blockIdx.x * TILE_L;

    // ---- loads: packed W/bias, F halo tile, scalars ----
    for (int i = tid; i < 2048; i += 256) {
        int c = i >> 5, o2 = i & 31;
        float w0 = W[(o2 * 2) * 64 + c];
        float w1 = W[(o2 * 2 + 1) * 64 + c];
        float2 bb = *(const float2*)&bias[c * 64 + o2 * 2];
        *(float4*)&WBs[i * 4] = make_float4(w0, w1, bb.x, bb.y);
    }
    const float* gF = F + (size_t)b * L_ * 64;
    for (int i = tid; i < ROWS_T * 16; i += 256) {
        int rr = i >> 4, cc = i & 15;
        int gl = tileStart - HALO + rr;
        float4 f = make_float4(0.f, 0.f, 0.f, 0.f);
        if (gl >= 0) f = ((const float4*)(gF + (size_t)gl * 64))[cc];
        ((float4*)Fs)[i] = f;
    }
    if (tid < ROWS_T + 1) {
        int kind = mask_kind((const unsigned char*)maskp);
        int gl = tileStart - HALO + tid;
        float t = 0.f, v = 0.f;
        if (gl >= 0 && gl < L_) {
            int mi = b * L_ + gl;
            t = times[mi];
            bool mv;
            if (kind == 0)      mv = ((const unsigned char*)maskp)[mi] != 0;
            else if (kind == 1) mv = ((const int*)maskp)[mi] != 0;
            else                mv = ((const float*)maskp)[mi] != 0.f;
            v = mv ? 1.f : 0.f;
        }
        ts[tid] = t;
        vsf[tid] = v;
    }
    if (tid < S_) us[tid] = usample[tid];
    __syncthreads();

    // ---- phase 1: GEMM tile into registers. thread = (o-pair o2, 9-row group rg) ----
    int o2 = tid & 31;          // o = 2*o2, 2*o2+1
    int rg = tid >> 5;          // warp-uniform -> Fs loads broadcast
    int row0 = rg * 9;

    u64 aP[9], aQ[9];
#pragma unroll
    for (int j = 0; j < 9; j++) { aP[j] = 0ull; aQ[j] = 0ull; }

#pragma unroll
    for (int c4 = 0; c4 < 16; c4++) {
        ulonglong2 wb[4];       // wb[cc].x = packed W pair, .y = packed bias pair
#pragma unroll
        for (int cc = 0; cc < 4; cc++)
            wb[cc] = *(const ulonglong2*)&WBs[((c4 * 4 + cc) << 7) + (o2 << 2)];
#pragma unroll
        for (int j = 0; j < 9; j++) {
            float4 fv = *(const float4*)&Fs[(row0 + j) * 64 + c4 * 4];
#pragma unroll
            for (int cc = 0; cc < 4; cc++) {
                u64 ff = splat2(((const float*)&fv)[cc]);
                fma2(aP[j], ff, wb[cc].x);
                fma2(aQ[j], ff, wb[cc].y);
            }
        }
    }
    __syncthreads();   // all WBs/Fs reads complete -> safe to overwrite (alias)

    // writeback with mask folded in: Ps = m_j*P, Qs = m_j*Q
#pragma unroll
    for (int j = 0; j < 9; j++) {
        u64 mm = splat2(vsf[row0 + j]);
        *(u64*)&Ps[(row0 + j) * 64 + o2 * 2] = mul2(aP[j], mm);
        *(u64*)&Qs[(row0 + j) * 64 + o2 * 2] = mul2(aQ[j], mm);
    }
    __syncthreads();

    // ---- phase 2: sliding-window combine ----
    // real[l] = m_l*(t_l*A + E),   A = sum_{j=l-8..l-1} mP_j,  E = sum (mQ_j - t_j*mP_j)
    // sim[l]  = m_l*(t_l*An + En), An/En = window advanced to j=l-7..l (8 taps)
    // sum_lin = m_l*An.  Carry (An,En) into the next l.
    {
        int o4 = (tid & 15) * 4;
        int l0 = (tid >> 4) * 4;   // local l of chunk start

        float4 A = make_float4(0.f, 0.f, 0.f, 0.f);
        float4 E = make_float4(0.f, 0.f, 0.f, 0.f);
#pragma unroll
        for (int i = 0; i < 8; i++) {          // init window j = l0-8 .. l0-1 (rows l0..l0+7)
            int r = l0 + i;
            float4 p = *(const float4*)&Ps[r * 64 + o4];
            float4 q = *(const float4*)&Qs[r * 64 + o4];
            float t = ts[r];
            A.x += p.x; A.y += p.y; A.z += p.z; A.w += p.w;
            E.x += fmaf(-t, p.x, q.x); E.y += fmaf(-t, p.y, q.y);
            E.z += fmaf(-t, p.z, q.z); E.w += fmaf(-t, p.w, q.w);
        }

#pragma unroll
        for (int i = 0; i < 4; i++) {
            int ll = l0 + i;
            int l = tileStart + ll;
            float tl = ts[ll + HALO];
            float m  = vsf[ll + HALO];

            float4 pn = *(const float4*)&Ps[(ll + HALO) * 64 + o4];   // new tap j=l
            float4 qn = *(const float4*)&Qs[(ll + HALO) * 64 + o4];
            float4 po = *(const float4*)&Ps[ll * 64 + o4];            // old tap j=l-8
            float4 qo = *(const float4*)&Qs[ll * 64 + o4];
            float to = ts[ll];

            // advanced 8-tap window j = l-7..l  (add new, drop old)
            float4 An, En;
            An.x = A.x + pn.x - po.x; An.y = A.y + pn.y - po.y;
            An.z = A.z + pn.z - po.z; An.w = A.w + pn.w - po.w;
            En.x = fmaf(to, po.x, fmaf(-tl, pn.x, E.x + qn.x) - qo.x);
            En.y = fmaf(to, po.y, fmaf(-tl, pn.y, E.y + qn.y) - qo.y);
            En.z = fmaf(to, po.z, fmaf(-tl, pn.z, E.z + qn.z) - qo.z);
            En.w = fmaf(to, po.w, fmaf(-tl, pn.w, E.w + qn.w) - qo.w);

            float4 re, sb, sl;
            re.x = m * fmaf(tl, A.x, E.x);   re.y = m * fmaf(tl, A.y, E.y);
            re.z = m * fmaf(tl, A.z, E.z);   re.w = m * fmaf(tl, A.w, E.w);
            sb.x = m * fmaf(tl, An.x, En.x); sb.y = m * fmaf(tl, An.y, En.y);
            sb.z = m * fmaf(tl, An.z, En.z); sb.w = m * fmaf(tl, An.w, En.w);
            sl.x = m * An.x; sl.y = m * An.y; sl.z = m * An.z; sl.w = m * An.w;

            float* ob = out + ((size_t)b * OUT_ROWS + (size_t)l * 9) * 64 + o4;
            *(float4*)ob = re;

            if (l < L_ - 1) {
                float udt = (m != 0.f && vsf[ll + HALO + 1] != 0.f)
                                ? (ts[ll + HALO + 1] - tl) : 0.f;
#pragma unroll
                for (int s = 0; s < S_; s++) {
                    float f = udt * us[s];
                    float4 v = make_float4(fmaf(f, sl.x, sb.x), fmaf(f, sl.y, sb.y),
                                           fmaf(f, sl.z, sb.z), fmaf(f, sl.w, sb.w));
                    *(float4*)(ob + (s + 1) * 64) = v;
                }
            }

            A = An;   // window for real[l+1] is exactly j = l-7..l
            E = En;
        }
    }
}

extern "C" void kernel_launch(void* const* d_in, const int* in_sizes, int n_in,
                              void* d_out, int out_size) {
    const float* times    = (const float*)d_in[0];
    const float* features = (const float*)d_in[1];
    const void*  mask     = d_in[2];
    const float* usample  = (const float*)d_in[3];
    const float* W        = (const float*)d_in[4];
    const float* bias     = (const float*)d_in[5];
    float* out = (float*)d_out;

    cudaFuncSetAttribute(fused_kernel, cudaFuncAttributeMaxDynamicSharedMemorySize,
                         (int)FUSED_SMEM);
    dim3 g(L_ / TILE_L, B_);
    fused_kernel<<<g, 256, FUSED_SMEM>>>(times, features, mask, usample, W, bias, out);
}